// round 5
// baseline (speedup 1.0000x reference)
#include <cuda_runtime.h>
#include <math.h>

#define N_LEVELS 16
#define HASHMAP_SIZE 32768
#define HASH_MASK 32767u
#define NPTS 524288
#define P1 2654435761u
#define P2 805459861u
#define MBITS 6                       // morton bits per dim
#define NBUCK (1 << (3 * MBITS))      // 262144 buckets

// Materialized per-level tables: [16][32768] x float2 (4 MB), 16B-aligned.
__device__ __align__(16) float2 g_tables[N_LEVELS * HASHMAP_SIZE];

// Counting-sort scratch
__device__ unsigned g_hist[NBUCK];
__device__ unsigned g_offs[NBUCK];
__device__ unsigned g_bucket[NPTS];
__device__ float4   g_sx[NPTS];       // sorted normalized coords
__device__ int      g_sidx[NPTS];     // sorted slot -> original point index

struct ResParams { float res[N_LEVELS]; };

// ---------------------------------------------------------------------------
// Kernel 1: tables[l][s][:] = A[l][s][0:4] @ B[l][0:4][0:2]
// ---------------------------------------------------------------------------
__global__ void __launch_bounds__(256) build_tables_kernel(
    const float* __restrict__ A, const float* __restrict__ B) {
    int idx = blockIdx.x * blockDim.x + threadIdx.x;
    int l = idx >> 15;
    float4 a = __ldg(reinterpret_cast<const float4*>(A) + idx);
    const float* b = B + l * 8;
    float f0 = a.x * b[0];
    f0 = fmaf(a.y, b[2], f0);
    f0 = fmaf(a.z, b[4], f0);
    f0 = fmaf(a.w, b[6], f0);
    float f1 = a.x * b[1];
    f1 = fmaf(a.y, b[3], f1);
    f1 = fmaf(a.z, b[5], f1);
    f1 = fmaf(a.w, b[7], f1);
    g_tables[idx] = make_float2(f0, f1);
}

// ---------------------------------------------------------------------------
// Morton helpers
// ---------------------------------------------------------------------------
__device__ __forceinline__ unsigned part1by2(unsigned v) {
    v &= 0x3FFu;
    v = (v | (v << 16)) & 0x030000FFu;
    v = (v | (v << 8))  & 0x0300F00Fu;
    v = (v | (v << 4))  & 0x030C30C3u;
    v = (v | (v << 2))  & 0x09249249u;
    return v;
}

__global__ void __launch_bounds__(256) zero_hist_kernel() {
    int i = blockIdx.x * blockDim.x + threadIdx.x;
    g_hist[i] = 0u;
}

__global__ void __launch_bounds__(256) hist_kernel(const float* __restrict__ x) {
    int n = blockIdx.x * blockDim.x + threadIdx.x;
    float xn0 = (__ldg(&x[3 * n + 0]) + 1.0f) * 0.5f;
    float xn1 = (__ldg(&x[3 * n + 1]) + 1.0f) * 0.5f;
    float xn2 = (__ldg(&x[3 * n + 2]) + 1.0f) * 0.5f;
    int cx = min(max((int)(xn0 * 64.0f), 0), 63);
    int cy = min(max((int)(xn1 * 64.0f), 0), 63);
    int cz = min(max((int)(xn2 * 64.0f), 0), 63);
    unsigned code = part1by2((unsigned)cx)
                  | (part1by2((unsigned)cy) << 1)
                  | (part1by2((unsigned)cz) << 2);
    g_bucket[n] = code;
    atomicAdd(&g_hist[code], 1u);
}

// Single-block exclusive scan of g_hist -> g_offs (1024 thr x 256 entries)
__global__ void __launch_bounds__(1024) scan_kernel() {
    __shared__ unsigned s[1024];
    int t = threadIdx.x;
    int base = t * (NBUCK / 1024);
    unsigned sum = 0;
    unsigned local[NBUCK / 1024];
#pragma unroll 8
    for (int i = 0; i < NBUCK / 1024; i++) {
        local[i] = g_hist[base + i];
        sum += local[i];
    }
    s[t] = sum;
    __syncthreads();
    // Hillis-Steele inclusive scan over 1024 partials
    for (int d = 1; d < 1024; d <<= 1) {
        unsigned v = (t >= d) ? s[t - d] : 0u;
        __syncthreads();
        s[t] += v;
        __syncthreads();
    }
    unsigned run = s[t] - sum;   // exclusive prefix for this thread
#pragma unroll 8
    for (int i = 0; i < NBUCK / 1024; i++) {
        g_offs[base + i] = run;
        run += local[i];
    }
}

__global__ void __launch_bounds__(256) scatter_kernel(const float* __restrict__ x) {
    int n = blockIdx.x * blockDim.x + threadIdx.x;
    float xn0 = (__ldg(&x[3 * n + 0]) + 1.0f) * 0.5f;
    float xn1 = (__ldg(&x[3 * n + 1]) + 1.0f) * 0.5f;
    float xn2 = (__ldg(&x[3 * n + 2]) + 1.0f) * 0.5f;
    unsigned code = g_bucket[n];
    unsigned pos = atomicAdd(&g_offs[code], 1u);
    g_sx[pos] = make_float4(xn0, xn1, xn2, 0.0f);
    g_sidx[pos] = n;
}

// ---------------------------------------------------------------------------
// Encode: thread = (sorted slot, half of levels). Morton order gives warps
// spatial locality -> cross-lane L1 line sharing at coarse levels.
// ---------------------------------------------------------------------------
__device__ __forceinline__ float2 lerp2(float2 a, float2 b, float t) {
    return make_float2(fmaf(t, b.x - a.x, a.x),
                       fmaf(t, b.y - a.y, a.y));
}

__global__ void __launch_bounds__(256) encode_kernel(
    float* __restrict__ out, ResParams p) {
    int tid = blockIdx.x * blockDim.x + threadIdx.x;   // 0 .. 2*NPTS-1
    int s    = tid >> 1;
    int half = tid & 1;
    int l0   = half << 3;

    float4 c = g_sx[s];
    int n = g_sidx[s];
    float xn0 = c.x, xn1 = c.y, xn2 = c.z;

    float4* o = reinterpret_cast<float4*>(out + (size_t)n * 32) + (half << 2);
    float2 prev;

#pragma unroll
    for (int k = 0; k < 8; k++) {
        int l = l0 + k;
        float r = p.res[l];
        float fx = xn0 * r, fy = xn1 * r, fz = xn2 * r;
        float flx = floorf(fx), fly = floorf(fy), flz = floorf(fz);
        float wx = fx - flx, wy = fy - fly, wz = fz - flz;
        unsigned ix = (unsigned)flx;
        unsigned iy = (unsigned)fly;
        unsigned iz = (unsigned)flz;

        unsigned hy0 = iy * P1;
        unsigned hy1 = hy0 + P1;
        unsigned hz0 = iz * P2;
        unsigned hz1 = hz0 + P2;
        unsigned r00 = hy0 ^ hz0;
        unsigned r10 = hy1 ^ hz0;
        unsigned r01 = hy0 ^ hz1;
        unsigned r11 = hy1 ^ hz1;

        const float2* tab = g_tables + (l << 15);
        float2 a00, b00, a10, b10, a01, b01, a11, b11;

        if ((ix & 1u) == 0u) {
            const float4* tab4 = reinterpret_cast<const float4*>(tab);
#define LOAD_PAIR(RYZ, AV, BV)                                              \
            {                                                               \
                unsigned i0 = (ix ^ (RYZ)) & HASH_MASK;                     \
                float4 q = __ldg(&tab4[i0 >> 1]);                           \
                float2 qlo = make_float2(q.x, q.y);                         \
                float2 qhi = make_float2(q.z, q.w);                         \
                bool sw = (i0 & 1u) != 0u;                                  \
                AV = sw ? qhi : qlo;                                        \
                BV = sw ? qlo : qhi;                                        \
            }
            LOAD_PAIR(r00, a00, b00)
            LOAD_PAIR(r10, a10, b10)
            LOAD_PAIR(r01, a01, b01)
            LOAD_PAIR(r11, a11, b11)
#undef LOAD_PAIR
        } else {
            unsigned x1 = ix + 1u;
            a00 = __ldg(&tab[(ix ^ r00) & HASH_MASK]);
            b00 = __ldg(&tab[(x1 ^ r00) & HASH_MASK]);
            a10 = __ldg(&tab[(ix ^ r10) & HASH_MASK]);
            b10 = __ldg(&tab[(x1 ^ r10) & HASH_MASK]);
            a01 = __ldg(&tab[(ix ^ r01) & HASH_MASK]);
            b01 = __ldg(&tab[(x1 ^ r01) & HASH_MASK]);
            a11 = __ldg(&tab[(ix ^ r11) & HASH_MASK]);
            b11 = __ldg(&tab[(x1 ^ r11) & HASH_MASK]);
        }

        float2 m00 = lerp2(a00, b00, wx);
        float2 m10 = lerp2(a10, b10, wx);
        float2 m01 = lerp2(a01, b01, wx);
        float2 m11 = lerp2(a11, b11, wx);
        float2 mm0 = lerp2(m00, m10, wy);
        float2 mm1 = lerp2(m01, m11, wy);
        float2 rr  = lerp2(mm0, mm1, wz);

        if ((k & 1) == 0) {
            prev = rr;
        } else {
            o[k >> 1] = make_float4(prev.x, prev.y, rr.x, rr.y);
        }
    }
}

// ---------------------------------------------------------------------------
// Launch
// ---------------------------------------------------------------------------
extern "C" void kernel_launch(void* const* d_in, const int* in_sizes, int n_in,
                              void* d_out, int out_size) {
    const float* x = (const float*)d_in[0];        // [524288, 3]
    const float* A = (const float*)d_in[1];        // [16, 32768, 4]
    const float* B = (const float*)d_in[2];        // [16, 4, 2]
    float* out = (float*)d_out;                    // [524288, 32]

    // Replicate numpy's resolution computation bit-exactly.
    ResParams p;
    double b = exp((log(512.0) - log(16.0)) / 15.0);
    for (int l = 0; l < N_LEVELS; l++) {
        double bl;
        if (l == 0)      bl = 1.0;
        else if (l == 1) bl = b;
        else if (l == 2) bl = b * b;
        else             bl = pow(b, (double)l);
        p.res[l] = (float)floor(16.0 * bl);
    }

    build_tables_kernel<<<(N_LEVELS * HASHMAP_SIZE) / 256, 256>>>(A, B);
    zero_hist_kernel<<<NBUCK / 256, 256>>>();
    hist_kernel<<<NPTS / 256, 256>>>(x);
    scan_kernel<<<1, 1024>>>();
    scatter_kernel<<<NPTS / 256, 256>>>(x);
    encode_kernel<<<(2 * NPTS) / 256, 256>>>(out, p);
}

// round 6
// speedup vs baseline: 3.4708x; 3.4708x over previous
#include <cuda_runtime.h>
#include <math.h>

#define N_LEVELS 16
#define HASHMAP_SIZE 32768
#define HASH_MASK 32767u
#define NPTS 524288
#define P1 2654435761u
#define P2 805459861u
#define MBITS 6                       // morton bits per dim
#define NBUCK (1 << (3 * MBITS))      // 262144 buckets

// Materialized per-level tables: [16][32768] x float2 (4 MB), 16B-aligned.
__device__ __align__(16) float2 g_tables[N_LEVELS * HASHMAP_SIZE];

// Counting-sort scratch
__device__ __align__(16) unsigned g_hist[NBUCK];
__device__ __align__(16) unsigned g_offs[NBUCK];
__device__ unsigned g_blk[256];
__device__ unsigned g_bucket[NPTS];
__device__ float4   g_sx[NPTS];       // sorted normalized coords
__device__ int      g_sidx[NPTS];     // sorted slot -> original point index

struct ResParams { float res[N_LEVELS]; };

// ---------------------------------------------------------------------------
// Kernel 1: tables[l][s][:] = A[l][s][0:4] @ B[l][0:4][0:2]
// ---------------------------------------------------------------------------
__global__ void __launch_bounds__(256) build_tables_kernel(
    const float* __restrict__ A, const float* __restrict__ B) {
    int idx = blockIdx.x * blockDim.x + threadIdx.x;
    int l = idx >> 15;
    float4 a = __ldg(reinterpret_cast<const float4*>(A) + idx);
    const float* b = B + l * 8;
    float f0 = a.x * b[0];
    f0 = fmaf(a.y, b[2], f0);
    f0 = fmaf(a.z, b[4], f0);
    f0 = fmaf(a.w, b[6], f0);
    float f1 = a.x * b[1];
    f1 = fmaf(a.y, b[3], f1);
    f1 = fmaf(a.z, b[5], f1);
    f1 = fmaf(a.w, b[7], f1);
    g_tables[idx] = make_float2(f0, f1);
}

// ---------------------------------------------------------------------------
// Morton helpers
// ---------------------------------------------------------------------------
__device__ __forceinline__ unsigned part1by2(unsigned v) {
    v &= 0x3FFu;
    v = (v | (v << 16)) & 0x030000FFu;
    v = (v | (v << 8))  & 0x0300F00Fu;
    v = (v | (v << 4))  & 0x030C30C3u;
    v = (v | (v << 2))  & 0x09249249u;
    return v;
}

__global__ void __launch_bounds__(256) zero_hist_kernel() {
    int i = blockIdx.x * blockDim.x + threadIdx.x;
    reinterpret_cast<uint4*>(g_hist)[i] = make_uint4(0u, 0u, 0u, 0u);
}

__global__ void __launch_bounds__(256) hist_kernel(const float* __restrict__ x) {
    int n = blockIdx.x * blockDim.x + threadIdx.x;
    float xn0 = (__ldg(&x[3 * n + 0]) + 1.0f) * 0.5f;
    float xn1 = (__ldg(&x[3 * n + 1]) + 1.0f) * 0.5f;
    float xn2 = (__ldg(&x[3 * n + 2]) + 1.0f) * 0.5f;
    int cx = min(max((int)(xn0 * 64.0f), 0), 63);
    int cy = min(max((int)(xn1 * 64.0f), 0), 63);
    int cz = min(max((int)(xn2 * 64.0f), 0), 63);
    unsigned code = part1by2((unsigned)cx)
                  | (part1by2((unsigned)cy) << 1)
                  | (part1by2((unsigned)cz) << 2);
    g_bucket[n] = code;
    atomicAdd(&g_hist[code], 1u);
}

// ---------------------------------------------------------------------------
// Hierarchical exclusive scan of g_hist (262144 entries) -> g_offs
// ---------------------------------------------------------------------------
__global__ void __launch_bounds__(256) scanA_kernel() {
    __shared__ unsigned s[256];
    int t = threadIdx.x;
    int base = blockIdx.x * 1024 + t * 4;
    uint4 v = reinterpret_cast<const uint4*>(g_hist)[base >> 2];
    unsigned sum = v.x + v.y + v.z + v.w;
    s[t] = sum;
    __syncthreads();
#pragma unroll
    for (int d = 1; d < 256; d <<= 1) {
        unsigned u = (t >= d) ? s[t - d] : 0u;
        __syncthreads();
        s[t] += u;
        __syncthreads();
    }
    unsigned ex = s[t] - sum;   // exclusive prefix within block
    uint4 o;
    o.x = ex;
    o.y = ex + v.x;
    o.z = o.y + v.y;
    o.w = o.z + v.z;
    reinterpret_cast<uint4*>(g_offs)[base >> 2] = o;
    if (t == 255) g_blk[blockIdx.x] = s[255];
}

__global__ void __launch_bounds__(256) scanB_kernel() {
    __shared__ unsigned s[256];
    int t = threadIdx.x;
    unsigned v = g_blk[t];
    s[t] = v;
    __syncthreads();
#pragma unroll
    for (int d = 1; d < 256; d <<= 1) {
        unsigned u = (t >= d) ? s[t - d] : 0u;
        __syncthreads();
        s[t] += u;
        __syncthreads();
    }
    g_blk[t] = s[t] - v;        // exclusive
}

__global__ void __launch_bounds__(256) scanC_kernel() {
    int t = threadIdx.x;
    unsigned add = g_blk[blockIdx.x];
    int i = (blockIdx.x * 1024 + t * 4) >> 2;
    uint4 v = reinterpret_cast<const uint4*>(g_offs)[i];
    v.x += add; v.y += add; v.z += add; v.w += add;
    reinterpret_cast<uint4*>(g_offs)[i] = v;
}

__global__ void __launch_bounds__(256) scatter_kernel(const float* __restrict__ x) {
    int n = blockIdx.x * blockDim.x + threadIdx.x;
    float xn0 = (__ldg(&x[3 * n + 0]) + 1.0f) * 0.5f;
    float xn1 = (__ldg(&x[3 * n + 1]) + 1.0f) * 0.5f;
    float xn2 = (__ldg(&x[3 * n + 2]) + 1.0f) * 0.5f;
    unsigned code = g_bucket[n];
    unsigned pos = atomicAdd(&g_offs[code], 1u);
    g_sx[pos] = make_float4(xn0, xn1, xn2, 0.0f);
    g_sidx[pos] = n;
}

// ---------------------------------------------------------------------------
// Encode: thread = (sorted slot, half of levels). Morton order gives warps
// spatial locality -> cross-lane L1 line sharing at coarse levels.
// ---------------------------------------------------------------------------
__device__ __forceinline__ float2 lerp2(float2 a, float2 b, float t) {
    return make_float2(fmaf(t, b.x - a.x, a.x),
                       fmaf(t, b.y - a.y, a.y));
}

__global__ void __launch_bounds__(256) encode_kernel(
    float* __restrict__ out, ResParams p) {
    int tid = blockIdx.x * blockDim.x + threadIdx.x;   // 0 .. 2*NPTS-1
    int s    = tid >> 1;
    int half = tid & 1;
    int l0   = half << 3;

    float4 c = g_sx[s];
    int n = g_sidx[s];
    float xn0 = c.x, xn1 = c.y, xn2 = c.z;

    float4* o = reinterpret_cast<float4*>(out + (size_t)n * 32) + (half << 2);
    float2 prev;

#pragma unroll
    for (int k = 0; k < 8; k++) {
        int l = l0 + k;
        float r = p.res[l];
        float fx = xn0 * r, fy = xn1 * r, fz = xn2 * r;
        float flx = floorf(fx), fly = floorf(fy), flz = floorf(fz);
        float wx = fx - flx, wy = fy - fly, wz = fz - flz;
        unsigned ix = (unsigned)flx;
        unsigned iy = (unsigned)fly;
        unsigned iz = (unsigned)flz;

        unsigned hy0 = iy * P1;
        unsigned hy1 = hy0 + P1;
        unsigned hz0 = iz * P2;
        unsigned hz1 = hz0 + P2;
        unsigned r00 = hy0 ^ hz0;
        unsigned r10 = hy1 ^ hz0;
        unsigned r01 = hy0 ^ hz1;
        unsigned r11 = hy1 ^ hz1;

        const float2* tab = g_tables + (l << 15);
        float2 a00, b00, a10, b10, a01, b01, a11, b11;

        if ((ix & 1u) == 0u) {
            const float4* tab4 = reinterpret_cast<const float4*>(tab);
#define LOAD_PAIR(RYZ, AV, BV)                                              \
            {                                                               \
                unsigned i0 = (ix ^ (RYZ)) & HASH_MASK;                     \
                float4 q = __ldg(&tab4[i0 >> 1]);                           \
                float2 qlo = make_float2(q.x, q.y);                         \
                float2 qhi = make_float2(q.z, q.w);                         \
                bool sw = (i0 & 1u) != 0u;                                  \
                AV = sw ? qhi : qlo;                                        \
                BV = sw ? qlo : qhi;                                        \
            }
            LOAD_PAIR(r00, a00, b00)
            LOAD_PAIR(r10, a10, b10)
            LOAD_PAIR(r01, a01, b01)
            LOAD_PAIR(r11, a11, b11)
#undef LOAD_PAIR
        } else {
            unsigned x1 = ix + 1u;
            a00 = __ldg(&tab[(ix ^ r00) & HASH_MASK]);
            b00 = __ldg(&tab[(x1 ^ r00) & HASH_MASK]);
            a10 = __ldg(&tab[(ix ^ r10) & HASH_MASK]);
            b10 = __ldg(&tab[(x1 ^ r10) & HASH_MASK]);
            a01 = __ldg(&tab[(ix ^ r01) & HASH_MASK]);
            b01 = __ldg(&tab[(x1 ^ r01) & HASH_MASK]);
            a11 = __ldg(&tab[(ix ^ r11) & HASH_MASK]);
            b11 = __ldg(&tab[(x1 ^ r11) & HASH_MASK]);
        }

        float2 m00 = lerp2(a00, b00, wx);
        float2 m10 = lerp2(a10, b10, wx);
        float2 m01 = lerp2(a01, b01, wx);
        float2 m11 = lerp2(a11, b11, wx);
        float2 mm0 = lerp2(m00, m10, wy);
        float2 mm1 = lerp2(m01, m11, wy);
        float2 rr  = lerp2(mm0, mm1, wz);

        if ((k & 1) == 0) {
            prev = rr;
        } else {
            o[k >> 1] = make_float4(prev.x, prev.y, rr.x, rr.y);
        }
    }
}

// ---------------------------------------------------------------------------
// Launch
// ---------------------------------------------------------------------------
extern "C" void kernel_launch(void* const* d_in, const int* in_sizes, int n_in,
                              void* d_out, int out_size) {
    const float* x = (const float*)d_in[0];        // [524288, 3]
    const float* A = (const float*)d_in[1];        // [16, 32768, 4]
    const float* B = (const float*)d_in[2];        // [16, 4, 2]
    float* out = (float*)d_out;                    // [524288, 32]

    // Replicate numpy's resolution computation bit-exactly.
    ResParams p;
    double b = exp((log(512.0) - log(16.0)) / 15.0);
    for (int l = 0; l < N_LEVELS; l++) {
        double bl;
        if (l == 0)      bl = 1.0;
        else if (l == 1) bl = b;
        else if (l == 2) bl = b * b;
        else             bl = pow(b, (double)l);
        p.res[l] = (float)floor(16.0 * bl);
    }

    build_tables_kernel<<<(N_LEVELS * HASHMAP_SIZE) / 256, 256>>>(A, B);
    zero_hist_kernel<<<NBUCK / 1024, 256>>>();
    hist_kernel<<<NPTS / 256, 256>>>(x);
    scanA_kernel<<<256, 256>>>();
    scanB_kernel<<<1, 256>>>();
    scanC_kernel<<<256, 256>>>();
    scatter_kernel<<<NPTS / 256, 256>>>(x);
    encode_kernel<<<(2 * NPTS) / 256, 256>>>(out, p);
}